// round 3
// baseline (speedup 1.0000x reference)
#include <cuda_runtime.h>

#define N_NODES 100000
#define N_EDGES 1600000
#define D 64

// Scratch (static __device__ — allocation-free per harness rules)
__device__ int   g_is64;             // 1 if edge_index is int64, 0 if int32
__device__ int   g_deg[N_NODES];
__device__ int   g_rowoff[N_NODES + 1];
__device__ int   g_cursor[N_NODES];
__device__ float g_dinv[N_NODES];
__device__ int   g_srcidx[N_EDGES];
__device__ float g_A[N_NODES * D];   // aggregated (mean) neighbor features
__device__ float g_H[N_NODES * D];   // layer-1 hidden

// ---------- edge_index dtype detection ----------
// int64 little-endian node ids (< 2^17) have all odd 32-bit words == 0.
// int32 ids are uniform in [0, 100000): P[32 odd words all zero] ~ 1e-160.
__global__ void k_detect(const int* __restrict__ ei32) {
    int odd_zero = 1;
#pragma unroll
    for (int i = 1; i < 64; i += 2)
        if (ei32[i] != 0) odd_zero = 0;
    g_is64 = odd_zero;
}

__device__ __forceinline__ int clampN(int v) {
    return min(max(v, 0), N_NODES - 1);
}
__device__ __forceinline__ int load_id(const void* ei, long long idx, int is64) {
    int v = is64 ? (int)((const long long*)ei)[idx] : ((const int*)ei)[idx];
    return clampN(v);
}

// ---------- CSR construction ----------
__global__ void k_zero() {
    int i = blockIdx.x * blockDim.x + threadIdx.x;
    if (i < N_NODES) g_deg[i] = 0;
}

__global__ void k_hist(const void* __restrict__ ei) {
    int e = blockIdx.x * blockDim.x + threadIdx.x;
    if (e < N_EDGES) {
        int is64 = g_is64;
        int dst = load_id(ei, (long long)N_EDGES + e, is64);
        atomicAdd(&g_deg[dst], 1);
    }
}

__global__ void k_scan() {
    __shared__ int ssum[1024];
    int t = threadIdx.x;
    const int CH = 98;  // 1024*98 >= 100000
    int lo = t * CH, hi = min(lo + CH, N_NODES);
    if (lo > N_NODES) lo = N_NODES;
    if (hi < lo) hi = lo;
    int s = 0;
    for (int i = lo; i < hi; i++) s += g_deg[i];
    ssum[t] = s;
    __syncthreads();
    for (int off = 1; off < 1024; off <<= 1) {
        int v = (t >= off) ? ssum[t - off] : 0;
        __syncthreads();
        ssum[t] += v;
        __syncthreads();
    }
    int run = (t == 0) ? 0 : ssum[t - 1];
    for (int i = lo; i < hi; i++) {
        g_rowoff[i] = run;
        g_cursor[i] = run;
        int d = g_deg[i];
        g_dinv[i] = 1.0f / (float)max(d, 1);
        run += d;
    }
    if (t == 0) g_rowoff[N_NODES] = N_EDGES;
}

__global__ void k_fill(const void* __restrict__ ei) {
    int e = blockIdx.x * blockDim.x + threadIdx.x;
    if (e < N_EDGES) {
        int is64 = g_is64;
        int dst = load_id(ei, (long long)N_EDGES + e, is64);
        int src = load_id(ei, e, is64);
        int pos = atomicAdd(&g_cursor[dst], 1);
        pos = min(max(pos, 0), N_EDGES - 1);
        g_srcidx[pos] = src;
    }
}

// ---------- mean aggregation: warp per node, no atomics ----------
template <bool FIRST>
__global__ void k_agg(const float* __restrict__ xext) {
    const float* __restrict__ feat = FIRST ? xext : (const float*)g_H;
    int gw = (blockIdx.x * blockDim.x + threadIdx.x) >> 5;
    int lane = threadIdx.x & 31;
    if (gw >= N_NODES) return;
    int s = g_rowoff[gw], e = g_rowoff[gw + 1];
    float ax = 0.f, ay = 0.f;
    int i = s;
    for (; i + 3 < e; i += 4) {   // MLP=4: 4 gathers in flight
        int s0 = g_srcidx[i], s1 = g_srcidx[i + 1];
        int s2 = g_srcidx[i + 2], s3 = g_srcidx[i + 3];
        float2 v0 = *(const float2*)&feat[s0 * D + lane * 2];
        float2 v1 = *(const float2*)&feat[s1 * D + lane * 2];
        float2 v2 = *(const float2*)&feat[s2 * D + lane * 2];
        float2 v3 = *(const float2*)&feat[s3 * D + lane * 2];
        ax += v0.x + v1.x + v2.x + v3.x;
        ay += v0.y + v1.y + v2.y + v3.y;
    }
    for (; i < e; i++) {
        int s0 = g_srcidx[i];
        float2 v = *(const float2*)&feat[s0 * D + lane * 2];
        ax += v.x; ay += v.y;
    }
    float di = g_dinv[gw];
    *(float2*)&g_A[gw * D + lane * 2] = make_float2(ax * di, ay * di);
}

// ---------- fused dual-linear: out = A@Wl^T + b + X@Wr^T (+relu) ----------
// 2 nodes per thread, plain fp32 FMAs, weights transposed pair-contiguous in SMEM.
template <bool FIRST>
__global__ void __launch_bounds__(256, 1)
k_dense(const float* __restrict__ xext,
        const float* __restrict__ Wl, const float* __restrict__ bias,
        const float* __restrict__ Wr, float* __restrict__ outext) {
    __shared__ float sWl[64 * 64];
    __shared__ float sWr[64 * 64];
    __shared__ float sb[64];
    const float* __restrict__ X = FIRST ? xext : (const float*)g_H;
    float* out = FIRST ? (float*)g_H : outext;
    int tid = threadIdx.x;
    for (int i = tid; i < 4096; i += 256) {
        int j = i >> 6, k = i & 63;
        sWl[k * 64 + j] = Wl[i];   // sW[k][j] = W[j][k]
        sWr[k * 64 + j] = Wr[i];
    }
    if (tid < 64) sb[tid] = bias[tid];
    __syncthreads();

    int n0 = blockIdx.x * 512 + tid;
    int n1 = n0 + 256;
    bool v0 = n0 < N_NODES, v1 = n1 < N_NODES;
    int m0 = v0 ? n0 : 0, m1 = v1 ? n1 : 0;

    float acc0[64], acc1[64];
#pragma unroll
    for (int j = 0; j < 64; j++) {
        float bb = sb[j];
        acc0[j] = bb; acc1[j] = bb;
    }
    const float4* A0 = (const float4*)(g_A + m0 * D);
    const float4* A1 = (const float4*)(g_A + m1 * D);
    const float4* X0 = (const float4*)(X + m0 * D);
    const float4* X1 = (const float4*)(X + m1 * D);

#pragma unroll 1
    for (int kq = 0; kq < 16; kq++) {
        float4 a0 = A0[kq], xq0 = X0[kq], a1 = A1[kq], xq1 = X1[kq];
        float fa0[4] = {a0.x, a0.y, a0.z, a0.w};
        float fx0[4] = {xq0.x, xq0.y, xq0.z, xq0.w};
        float fa1[4] = {a1.x, a1.y, a1.z, a1.w};
        float fx1[4] = {xq1.x, xq1.y, xq1.z, xq1.w};
#pragma unroll
        for (int kk = 0; kk < 4; kk++) {
            int k = kq * 4 + kk;
            float va0 = fa0[kk], vx0 = fx0[kk];
            float va1 = fa1[kk], vx1 = fx1[kk];
            const float2* wlp = (const float2*)&sWl[k * 64];
            const float2* wrp = (const float2*)&sWr[k * 64];
#pragma unroll
            for (int jj = 0; jj < 32; jj++) {
                float2 wl = wlp[jj], wr = wrp[jj];   // broadcast LDS.64
                acc0[2 * jj]     = fmaf(wl.x, va0, fmaf(wr.x, vx0, acc0[2 * jj]));
                acc0[2 * jj + 1] = fmaf(wl.y, va0, fmaf(wr.y, vx0, acc0[2 * jj + 1]));
                acc1[2 * jj]     = fmaf(wl.x, va1, fmaf(wr.x, vx1, acc1[2 * jj]));
                acc1[2 * jj + 1] = fmaf(wl.y, va1, fmaf(wr.y, vx1, acc1[2 * jj + 1]));
            }
        }
    }

    if (v0) {
        float4* o = (float4*)(out + n0 * D);
#pragma unroll
        for (int q = 0; q < 16; q++) {
            float r0 = acc0[4 * q],     r1 = acc0[4 * q + 1];
            float r2 = acc0[4 * q + 2], r3 = acc0[4 * q + 3];
            if (FIRST) {
                r0 = fmaxf(r0, 0.f); r1 = fmaxf(r1, 0.f);
                r2 = fmaxf(r2, 0.f); r3 = fmaxf(r3, 0.f);
            }
            o[q] = make_float4(r0, r1, r2, r3);
        }
    }
    if (v1) {
        float4* o = (float4*)(out + n1 * D);
#pragma unroll
        for (int q = 0; q < 16; q++) {
            float r0 = acc1[4 * q],     r1 = acc1[4 * q + 1];
            float r2 = acc1[4 * q + 2], r3 = acc1[4 * q + 3];
            if (FIRST) {
                r0 = fmaxf(r0, 0.f); r1 = fmaxf(r1, 0.f);
                r2 = fmaxf(r2, 0.f); r3 = fmaxf(r3, 0.f);
            }
            o[q] = make_float4(r0, r1, r2, r3);
        }
    }
}

extern "C" void kernel_launch(void* const* d_in, const int* in_sizes, int n_in,
                              void* d_out, int out_size) {
    const float* x   = (const float*)d_in[0];
    const void*  ei  = d_in[1];
    const float* W1l = (const float*)d_in[2];
    const float* b1  = (const float*)d_in[3];
    const float* W1r = (const float*)d_in[4];
    const float* W2l = (const float*)d_in[5];
    const float* b2  = (const float*)d_in[6];
    const float* W2r = (const float*)d_in[7];
    float* out = (float*)d_out;

    // Detect int32 vs int64 edge_index, then CSR build
    k_detect<<<1, 1>>>((const int*)ei);
    k_zero<<<(N_NODES + 255) / 256, 256>>>();
    k_hist<<<(N_EDGES + 255) / 256, 256>>>(ei);
    k_scan<<<1, 1024>>>();
    k_fill<<<(N_EDGES + 255) / 256, 256>>>(ei);

    // Layer 1
    k_agg<true><<<(N_NODES * 32 + 255) / 256, 256>>>(x);
    k_dense<true><<<(N_NODES + 511) / 512, 256>>>(x, W1l, b1, W1r, nullptr);

    // Layer 2
    k_agg<false><<<(N_NODES * 32 + 255) / 256, 256>>>(x);
    k_dense<false><<<(N_NODES + 511) / 512, 256>>>(x, W2l, b2, W2r, out);
}

// round 4
// speedup vs baseline: 1.7446x; 1.7446x over previous
#include <cuda_runtime.h>

#define N_NODES 100000
#define N_EDGES 1600000
#define D 64
#define SCAN_NB 391   // 391*256 = 100096 >= N_NODES

// Scratch (static __device__ — allocation-free per harness rules)
__device__ int   g_is64;             // 1 if edge_index is int64, 0 if int32
__device__ int   g_deg[N_NODES];
__device__ int   g_rowoff[N_NODES + 1];
__device__ int   g_cursor[N_NODES];
__device__ float g_dinv[N_NODES];
__device__ int   g_srcidx[N_EDGES];
__device__ int   g_bsum[512];
__device__ int   g_boff[512];
__device__ float g_A[N_NODES * D];   // aggregated (mean) neighbor features
__device__ float g_H[N_NODES * D];   // layer-1 hidden

// ---------- edge_index dtype detection ----------
// int64 little-endian node ids (< 2^17) have all odd 32-bit words == 0.
// int32 ids are uniform in [0, 100000): P[32 odd words all zero] ~ 1e-160.
__global__ void k_detect(const int* __restrict__ ei32) {
    int odd_zero = 1;
#pragma unroll
    for (int i = 1; i < 64; i += 2)
        if (ei32[i] != 0) odd_zero = 0;
    g_is64 = odd_zero;
}

__device__ __forceinline__ int clampN(int v) {
    return min(max(v, 0), N_NODES - 1);
}
__device__ __forceinline__ int load_id(const void* ei, long long idx, int is64) {
    int v = is64 ? (int)((const long long*)ei)[idx] : ((const int*)ei)[idx];
    return clampN(v);
}

// ---------- CSR construction ----------
__global__ void k_zero() {
    int i = blockIdx.x * blockDim.x + threadIdx.x;
    if (i < N_NODES) g_deg[i] = 0;
}

__global__ void k_hist(const void* __restrict__ ei) {
    int e = blockIdx.x * blockDim.x + threadIdx.x;
    if (e < N_EDGES) {
        int is64 = g_is64;
        int dst = load_id(ei, (long long)N_EDGES + e, is64);
        atomicAdd(&g_deg[dst], 1);
    }
}

// 3-phase parallel exclusive scan of g_deg -> g_rowoff/g_cursor (+dinv)
__global__ void k_scan1() {
    __shared__ int sh[256];
    int i = blockIdx.x * 256 + threadIdx.x;
    int t = threadIdx.x;
    sh[t] = (i < N_NODES) ? g_deg[i] : 0;
    __syncthreads();
    for (int off = 128; off > 0; off >>= 1) {
        if (t < off) sh[t] += sh[t + off];
        __syncthreads();
    }
    if (t == 0) g_bsum[blockIdx.x] = sh[0];
}

__global__ void k_scan2() {   // 1 block, 512 threads: scan block sums
    __shared__ int sh[512];
    int t = threadIdx.x;
    sh[t] = (t < SCAN_NB) ? g_bsum[t] : 0;
    __syncthreads();
    for (int off = 1; off < 512; off <<= 1) {
        int v = (t >= off) ? sh[t - off] : 0;
        __syncthreads();
        sh[t] += v;
        __syncthreads();
    }
    if (t < SCAN_NB) g_boff[t] = (t == 0) ? 0 : sh[t - 1];
}

__global__ void k_scan3() {
    __shared__ int sh[256];
    int b = blockIdx.x;
    int t = threadIdx.x;
    int i = b * 256 + t;
    int d = (i < N_NODES) ? g_deg[i] : 0;
    sh[t] = d;
    __syncthreads();
    for (int off = 1; off < 256; off <<= 1) {
        int v = (t >= off) ? sh[t - off] : 0;
        __syncthreads();
        sh[t] += v;
        __syncthreads();
    }
    if (i < N_NODES) {
        int excl = sh[t] - d + g_boff[b];
        g_rowoff[i] = excl;
        g_cursor[i] = excl;
        g_dinv[i] = 1.0f / (float)max(d, 1);
    }
    if (i == 0) g_rowoff[N_NODES] = N_EDGES;
}

__global__ void k_fill(const void* __restrict__ ei) {
    int e = blockIdx.x * blockDim.x + threadIdx.x;
    if (e < N_EDGES) {
        int is64 = g_is64;
        int dst = load_id(ei, (long long)N_EDGES + e, is64);
        int src = load_id(ei, e, is64);
        int pos = atomicAdd(&g_cursor[dst], 1);
        pos = min(max(pos, 0), N_EDGES - 1);
        g_srcidx[pos] = src;
    }
}

// ---------- mean aggregation: warp per node, no atomics ----------
template <bool FIRST>
__global__ void k_agg(const float* __restrict__ xext) {
    const float* __restrict__ feat = FIRST ? xext : (const float*)g_H;
    int gw = (blockIdx.x * blockDim.x + threadIdx.x) >> 5;
    int lane = threadIdx.x & 31;
    if (gw >= N_NODES) return;
    int s = g_rowoff[gw], e = g_rowoff[gw + 1];
    float ax = 0.f, ay = 0.f;
    int i = s;
    for (; i + 3 < e; i += 4) {   // MLP=4: 4 gathers in flight
        int s0 = g_srcidx[i], s1 = g_srcidx[i + 1];
        int s2 = g_srcidx[i + 2], s3 = g_srcidx[i + 3];
        float2 v0 = *(const float2*)&feat[s0 * D + lane * 2];
        float2 v1 = *(const float2*)&feat[s1 * D + lane * 2];
        float2 v2 = *(const float2*)&feat[s2 * D + lane * 2];
        float2 v3 = *(const float2*)&feat[s3 * D + lane * 2];
        ax += v0.x + v1.x + v2.x + v3.x;
        ay += v0.y + v1.y + v2.y + v3.y;
    }
    for (; i < e; i++) {
        int s0 = g_srcidx[i];
        float2 v = *(const float2*)&feat[s0 * D + lane * 2];
        ax += v.x; ay += v.y;
    }
    float di = g_dinv[gw];
    *(float2*)&g_A[gw * D + lane * 2] = make_float2(ax * di, ay * di);
}

// ---------- fused dual-linear: out = A@Wl^T + b + X@Wr^T (+relu) ----------
// 2 nodes per thread, plain fp32 FMAs, weights transposed pair-contiguous in SMEM.
template <bool FIRST>
__global__ void __launch_bounds__(256, 1)
k_dense(const float* __restrict__ xext,
        const float* __restrict__ Wl, const float* __restrict__ bias,
        const float* __restrict__ Wr, float* __restrict__ outext) {
    __shared__ float sWl[64 * 64];
    __shared__ float sWr[64 * 64];
    __shared__ float sb[64];
    const float* __restrict__ X = FIRST ? xext : (const float*)g_H;
    float* out = FIRST ? (float*)g_H : outext;
    int tid = threadIdx.x;
    for (int i = tid; i < 4096; i += 256) {
        int j = i >> 6, k = i & 63;
        sWl[k * 64 + j] = Wl[i];   // sW[k][j] = W[j][k]
        sWr[k * 64 + j] = Wr[i];
    }
    if (tid < 64) sb[tid] = bias[tid];
    __syncthreads();

    int n0 = blockIdx.x * 512 + tid;
    int n1 = n0 + 256;
    bool v0 = n0 < N_NODES, v1 = n1 < N_NODES;
    int m0 = v0 ? n0 : 0, m1 = v1 ? n1 : 0;

    float acc0[64], acc1[64];
#pragma unroll
    for (int j = 0; j < 64; j++) {
        float bb = sb[j];
        acc0[j] = bb; acc1[j] = bb;
    }
    const float4* A0 = (const float4*)(g_A + m0 * D);
    const float4* A1 = (const float4*)(g_A + m1 * D);
    const float4* X0 = (const float4*)(X + m0 * D);
    const float4* X1 = (const float4*)(X + m1 * D);

#pragma unroll 1
    for (int kq = 0; kq < 16; kq++) {
        float4 a0 = A0[kq], xq0 = X0[kq], a1 = A1[kq], xq1 = X1[kq];
        float fa0[4] = {a0.x, a0.y, a0.z, a0.w};
        float fx0[4] = {xq0.x, xq0.y, xq0.z, xq0.w};
        float fa1[4] = {a1.x, a1.y, a1.z, a1.w};
        float fx1[4] = {xq1.x, xq1.y, xq1.z, xq1.w};
#pragma unroll
        for (int kk = 0; kk < 4; kk++) {
            int k = kq * 4 + kk;
            float va0 = fa0[kk], vx0 = fx0[kk];
            float va1 = fa1[kk], vx1 = fx1[kk];
            const float2* wlp = (const float2*)&sWl[k * 64];
            const float2* wrp = (const float2*)&sWr[k * 64];
#pragma unroll
            for (int jj = 0; jj < 32; jj++) {
                float2 wl = wlp[jj], wr = wrp[jj];   // broadcast LDS.64
                acc0[2 * jj]     = fmaf(wl.x, va0, fmaf(wr.x, vx0, acc0[2 * jj]));
                acc0[2 * jj + 1] = fmaf(wl.y, va0, fmaf(wr.y, vx0, acc0[2 * jj + 1]));
                acc1[2 * jj]     = fmaf(wl.x, va1, fmaf(wr.x, vx1, acc1[2 * jj]));
                acc1[2 * jj + 1] = fmaf(wl.y, va1, fmaf(wr.y, vx1, acc1[2 * jj + 1]));
            }
        }
    }

    if (v0) {
        float4* o = (float4*)(out + n0 * D);
#pragma unroll
        for (int q = 0; q < 16; q++) {
            float r0 = acc0[4 * q],     r1 = acc0[4 * q + 1];
            float r2 = acc0[4 * q + 2], r3 = acc0[4 * q + 3];
            if (FIRST) {
                r0 = fmaxf(r0, 0.f); r1 = fmaxf(r1, 0.f);
                r2 = fmaxf(r2, 0.f); r3 = fmaxf(r3, 0.f);
            }
            o[q] = make_float4(r0, r1, r2, r3);
        }
    }
    if (v1) {
        float4* o = (float4*)(out + n1 * D);
#pragma unroll
        for (int q = 0; q < 16; q++) {
            float r0 = acc1[4 * q],     r1 = acc1[4 * q + 1];
            float r2 = acc1[4 * q + 2], r3 = acc1[4 * q + 3];
            if (FIRST) {
                r0 = fmaxf(r0, 0.f); r1 = fmaxf(r1, 0.f);
                r2 = fmaxf(r2, 0.f); r3 = fmaxf(r3, 0.f);
            }
            o[q] = make_float4(r0, r1, r2, r3);
        }
    }
}

extern "C" void kernel_launch(void* const* d_in, const int* in_sizes, int n_in,
                              void* d_out, int out_size) {
    const float* x   = (const float*)d_in[0];
    const void*  ei  = d_in[1];
    const float* W1l = (const float*)d_in[2];
    const float* b1  = (const float*)d_in[3];
    const float* W1r = (const float*)d_in[4];
    const float* W2l = (const float*)d_in[5];
    const float* b2  = (const float*)d_in[6];
    const float* W2r = (const float*)d_in[7];
    float* out = (float*)d_out;

    // Detect int32 vs int64 edge_index, then CSR build
    k_detect<<<1, 1>>>((const int*)ei);
    k_zero<<<(N_NODES + 255) / 256, 256>>>();
    k_hist<<<(N_EDGES + 255) / 256, 256>>>(ei);
    k_scan1<<<SCAN_NB, 256>>>();
    k_scan2<<<1, 512>>>();
    k_scan3<<<SCAN_NB, 256>>>();
    k_fill<<<(N_EDGES + 255) / 256, 256>>>(ei);

    // Layer 1
    k_agg<true><<<(N_NODES * 32 + 255) / 256, 256>>>(x);
    k_dense<true><<<(N_NODES + 511) / 512, 256>>>(x, W1l, b1, W1r, nullptr);

    // Layer 2
    k_agg<false><<<(N_NODES * 32 + 255) / 256, 256>>>(x);
    k_dense<false><<<(N_NODES + 511) / 512, 256>>>(x, W2l, b2, W2r, out);
}

// round 5
// speedup vs baseline: 1.9779x; 1.1337x over previous
#include <cuda_runtime.h>

#define N_NODES 100000
#define N_EDGES 1600000
#define D 64
#define SCAN_NB 391   // 391*256 = 100096 >= N_NODES

typedef unsigned long long ull;

// Scratch (static __device__ — allocation-free per harness rules)
__device__ int   g_is64;             // 1 if edge_index is int64, 0 if int32
__device__ int   g_deg[N_NODES];
__device__ int   g_rowoff[N_NODES + 1];
__device__ int   g_cursor[N_NODES];
__device__ float g_dinv[N_NODES];
__device__ int   g_srcidx[N_EDGES];
__device__ int   g_bsum[512];
__device__ int   g_boff[512];
__device__ float g_A[N_NODES * D];   // aggregated (mean) neighbor features
__device__ float g_H[N_NODES * D];   // layer-1 hidden

// ---------- packed f32x2 helpers ----------
__device__ __forceinline__ ull fma2(ull a, ull b, ull c) {
    ull d;
    asm("fma.rn.f32x2 %0, %1, %2, %3;" : "=l"(d) : "l"(a), "l"(b), "l"(c));
    return d;
}
__device__ __forceinline__ ull pack2(float x, float y) {
    ull d;
    asm("mov.b64 %0, {%1, %2};" : "=l"(d) : "f"(x), "f"(y));
    return d;
}
__device__ __forceinline__ void unpack2(ull v, float& x, float& y) {
    asm("mov.b64 {%0, %1}, %2;" : "=f"(x), "=f"(y) : "l"(v));
}

// ---------- edge_index dtype detection ----------
__global__ void k_detect(const int* __restrict__ ei32) {
    int odd_zero = 1;
#pragma unroll
    for (int i = 1; i < 64; i += 2)
        if (ei32[i] != 0) odd_zero = 0;
    g_is64 = odd_zero;
}

__device__ __forceinline__ int clampN(int v) {
    return min(max(v, 0), N_NODES - 1);
}
__device__ __forceinline__ int load_id(const void* ei, long long idx, int is64) {
    int v = is64 ? (int)((const long long*)ei)[idx] : ((const int*)ei)[idx];
    return clampN(v);
}

// ---------- CSR construction ----------
__global__ void k_zero() {
    int i = blockIdx.x * blockDim.x + threadIdx.x;
    if (i < N_NODES) g_deg[i] = 0;
}

__global__ void k_hist(const void* __restrict__ ei) {
    int e = blockIdx.x * blockDim.x + threadIdx.x;
    if (e < N_EDGES) {
        int is64 = g_is64;
        int dst = load_id(ei, (long long)N_EDGES + e, is64);
        atomicAdd(&g_deg[dst], 1);
    }
}

__global__ void k_scan1() {
    __shared__ int sh[256];
    int i = blockIdx.x * 256 + threadIdx.x;
    int t = threadIdx.x;
    sh[t] = (i < N_NODES) ? g_deg[i] : 0;
    __syncthreads();
    for (int off = 128; off > 0; off >>= 1) {
        if (t < off) sh[t] += sh[t + off];
        __syncthreads();
    }
    if (t == 0) g_bsum[blockIdx.x] = sh[0];
}

__global__ void k_scan2() {   // 1 block, 512 threads: scan block sums
    __shared__ int sh[512];
    int t = threadIdx.x;
    sh[t] = (t < SCAN_NB) ? g_bsum[t] : 0;
    __syncthreads();
    for (int off = 1; off < 512; off <<= 1) {
        int v = (t >= off) ? sh[t - off] : 0;
        __syncthreads();
        sh[t] += v;
        __syncthreads();
    }
    if (t < SCAN_NB) g_boff[t] = (t == 0) ? 0 : sh[t - 1];
}

__global__ void k_scan3() {
    __shared__ int sh[256];
    int b = blockIdx.x;
    int t = threadIdx.x;
    int i = b * 256 + t;
    int d = (i < N_NODES) ? g_deg[i] : 0;
    sh[t] = d;
    __syncthreads();
    for (int off = 1; off < 256; off <<= 1) {
        int v = (t >= off) ? sh[t - off] : 0;
        __syncthreads();
        sh[t] += v;
        __syncthreads();
    }
    if (i < N_NODES) {
        int excl = sh[t] - d + g_boff[b];
        g_rowoff[i] = excl;
        g_cursor[i] = excl;
        g_dinv[i] = 1.0f / (float)max(d, 1);
    }
    if (i == 0) g_rowoff[N_NODES] = N_EDGES;
}

__global__ void k_fill(const void* __restrict__ ei) {
    int e = blockIdx.x * blockDim.x + threadIdx.x;
    if (e < N_EDGES) {
        int is64 = g_is64;
        int dst = load_id(ei, (long long)N_EDGES + e, is64);
        int src = load_id(ei, e, is64);
        int pos = atomicAdd(&g_cursor[dst], 1);
        pos = min(max(pos, 0), N_EDGES - 1);
        g_srcidx[pos] = src;
    }
}

// ---------- mean aggregation: warp per node, no atomics ----------
template <bool FIRST>
__global__ void k_agg(const float* __restrict__ xext) {
    const float* __restrict__ feat = FIRST ? xext : (const float*)g_H;
    int gw = (blockIdx.x * blockDim.x + threadIdx.x) >> 5;
    int lane = threadIdx.x & 31;
    if (gw >= N_NODES) return;
    int s = g_rowoff[gw], e = g_rowoff[gw + 1];
    float ax = 0.f, ay = 0.f;
    int i = s;
    for (; i + 3 < e; i += 4) {   // MLP=4: 4 gathers in flight
        int s0 = g_srcidx[i], s1 = g_srcidx[i + 1];
        int s2 = g_srcidx[i + 2], s3 = g_srcidx[i + 3];
        float2 v0 = *(const float2*)&feat[s0 * D + lane * 2];
        float2 v1 = *(const float2*)&feat[s1 * D + lane * 2];
        float2 v2 = *(const float2*)&feat[s2 * D + lane * 2];
        float2 v3 = *(const float2*)&feat[s3 * D + lane * 2];
        ax += v0.x + v1.x + v2.x + v3.x;
        ay += v0.y + v1.y + v2.y + v3.y;
    }
    for (; i < e; i++) {
        int s0 = g_srcidx[i];
        float2 v = *(const float2*)&feat[s0 * D + lane * 2];
        ax += v.x; ay += v.y;
    }
    float di = g_dinv[gw];
    *(float2*)&g_A[gw * D + lane * 2] = make_float2(ax * di, ay * di);
}

// ---------- fused dual-linear: out = A@Wl^T + b + X@Wr^T (+relu) ----------
// 128 threads/block, 2 nodes/thread (256 nodes/block), packed FFMA2,
// LDS.128 weight loads (2 output pairs per load).
template <bool FIRST>
__global__ void __launch_bounds__(128)
k_dense(const float* __restrict__ xext,
        const float* __restrict__ Wl, const float* __restrict__ bias,
        const float* __restrict__ Wr, float* __restrict__ outext) {
    __shared__ float sWl[64 * 64];
    __shared__ float sWr[64 * 64];
    __shared__ float sb[64];
    const float* __restrict__ X = FIRST ? xext : (const float*)g_H;
    float* out = FIRST ? (float*)g_H : outext;
    int tid = threadIdx.x;
    for (int i = tid; i < 4096; i += 128) {
        int j = i >> 6, k = i & 63;
        sWl[k * 64 + j] = Wl[i];   // sW[k][j] = W[j][k]
        sWr[k * 64 + j] = Wr[i];
    }
    if (tid < 64) sb[tid] = bias[tid];
    __syncthreads();

    int n0 = blockIdx.x * 256 + tid;
    int n1 = n0 + 128;
    bool v0 = n0 < N_NODES, v1 = n1 < N_NODES;
    int m0 = v0 ? n0 : 0, m1 = v1 ? n1 : 0;

    ull acc0[32], acc1[32];
#pragma unroll
    for (int j = 0; j < 32; j++) {
        ull bb = pack2(sb[2 * j], sb[2 * j + 1]);
        acc0[j] = bb; acc1[j] = bb;
    }
    const float4* A0 = (const float4*)(g_A + m0 * D);
    const float4* A1 = (const float4*)(g_A + m1 * D);
    const float4* X0 = (const float4*)(X + m0 * D);
    const float4* X1 = (const float4*)(X + m1 * D);

#pragma unroll 1
    for (int kq = 0; kq < 16; kq++) {
        float4 a0 = A0[kq], xq0 = X0[kq], a1 = A1[kq], xq1 = X1[kq];
        float fa0[4] = {a0.x, a0.y, a0.z, a0.w};
        float fx0[4] = {xq0.x, xq0.y, xq0.z, xq0.w};
        float fa1[4] = {a1.x, a1.y, a1.z, a1.w};
        float fx1[4] = {xq1.x, xq1.y, xq1.z, xq1.w};
#pragma unroll
        for (int kk = 0; kk < 4; kk++) {
            int k = kq * 4 + kk;
            ull pa0 = pack2(fa0[kk], fa0[kk]);
            ull px0 = pack2(fx0[kk], fx0[kk]);
            ull pa1 = pack2(fa1[kk], fa1[kk]);
            ull px1 = pack2(fx1[kk], fx1[kk]);
            const ulonglong2* wlp = (const ulonglong2*)&sWl[k * 64];
            const ulonglong2* wrp = (const ulonglong2*)&sWr[k * 64];
#pragma unroll
            for (int jp = 0; jp < 16; jp++) {
                ulonglong2 wl = wlp[jp];   // LDS.128 broadcast
                ulonglong2 wr = wrp[jp];
                acc0[2 * jp]     = fma2(wl.x, pa0, fma2(wr.x, px0, acc0[2 * jp]));
                acc0[2 * jp + 1] = fma2(wl.y, pa0, fma2(wr.y, px0, acc0[2 * jp + 1]));
                acc1[2 * jp]     = fma2(wl.x, pa1, fma2(wr.x, px1, acc1[2 * jp]));
                acc1[2 * jp + 1] = fma2(wl.y, pa1, fma2(wr.y, px1, acc1[2 * jp + 1]));
            }
        }
    }

    if (v0) {
        float4* o = (float4*)(out + n0 * D);
#pragma unroll
        for (int q = 0; q < 16; q++) {
            float r0, r1, r2, r3;
            unpack2(acc0[2 * q], r0, r1);
            unpack2(acc0[2 * q + 1], r2, r3);
            if (FIRST) {
                r0 = fmaxf(r0, 0.f); r1 = fmaxf(r1, 0.f);
                r2 = fmaxf(r2, 0.f); r3 = fmaxf(r3, 0.f);
            }
            o[q] = make_float4(r0, r1, r2, r3);
        }
    }
    if (v1) {
        float4* o = (float4*)(out + n1 * D);
#pragma unroll
        for (int q = 0; q < 16; q++) {
            float r0, r1, r2, r3;
            unpack2(acc1[2 * q], r0, r1);
            unpack2(acc1[2 * q + 1], r2, r3);
            if (FIRST) {
                r0 = fmaxf(r0, 0.f); r1 = fmaxf(r1, 0.f);
                r2 = fmaxf(r2, 0.f); r3 = fmaxf(r3, 0.f);
            }
            o[q] = make_float4(r0, r1, r2, r3);
        }
    }
}

extern "C" void kernel_launch(void* const* d_in, const int* in_sizes, int n_in,
                              void* d_out, int out_size) {
    const float* x   = (const float*)d_in[0];
    const void*  ei  = d_in[1];
    const float* W1l = (const float*)d_in[2];
    const float* b1  = (const float*)d_in[3];
    const float* W1r = (const float*)d_in[4];
    const float* W2l = (const float*)d_in[5];
    const float* b2  = (const float*)d_in[6];
    const float* W2r = (const float*)d_in[7];
    float* out = (float*)d_out;

    // Detect int32 vs int64 edge_index, then CSR build
    k_detect<<<1, 1>>>((const int*)ei);
    k_zero<<<(N_NODES + 255) / 256, 256>>>();
    k_hist<<<(N_EDGES + 255) / 256, 256>>>(ei);
    k_scan1<<<SCAN_NB, 256>>>();
    k_scan2<<<1, 512>>>();
    k_scan3<<<SCAN_NB, 256>>>();
    k_fill<<<(N_EDGES + 255) / 256, 256>>>(ei);

    const int DNB = (N_NODES + 255) / 256;   // 391 blocks of 128 threads

    // Layer 1
    k_agg<true><<<(N_NODES * 32 + 255) / 256, 256>>>(x);
    k_dense<true><<<DNB, 128>>>(x, W1l, b1, W1r, nullptr);

    // Layer 2
    k_agg<false><<<(N_NODES * 32 + 255) / 256, 256>>>(x);
    k_dense<false><<<DNB, 128>>>(x, W2l, b2, W2r, out);
}